// round 13
// baseline (speedup 1.0000x reference)
#include <cuda_runtime.h>

#define FOV_TAN 0.57735026918962576451f   // tan(30 deg)
#define HALF    1.494140625f              // 255 * (3/256) * 0.5
#define NC      8                         // depth chunks (finer for balance)
#define CSTEP   40                        // 320 / NC
#define NPIX    65536
#define DSTEP   (4.0f / 319.0f)           // linspace(2,6,320) step
#define PIPE    3                         // interior pipeline width

// ---- scratch (static device arrays; no allocations allowed) ----
__device__ float g_cRGB[NC * NPIX];
__device__ float g_cT[NC * NPIX];
__device__ float g_gray[NPIX];
__device__ float g_psum[256], g_psq[256], g_pmin[256], g_pmax[256];
__device__ float g_scal[4];          // mean, sigma+eps, stdmin, denom
__device__ unsigned g_cnt = 0;       // self-resetting last-block counter

// Intersect f(p) = c0 + s*p with [0, 255]; accumulate into [tlo, thi].
__device__ __forceinline__ void axis_bounds(float c0, float s, float& tlo, float& thi)
{
    if (s > 0.0f) {
        tlo = fmaxf(tlo, (0.0f   - c0) / s);
        thi = fminf(thi, (255.0f - c0) / s);
    } else if (s < 0.0f) {
        tlo = fmaxf(tlo, (255.0f - c0) / s);
        thi = fminf(thi, (0.0f   - c0) / s);
    } else if (c0 < 0.0f || c0 > 255.0f) {
        tlo = 1e30f; thi = -1e30f;
    }
}

// Masked-path sample: coords -> clamped base + weights + inside mask.
__device__ __forceinline__ void sample_setup(
    float fp, float sx, float sy, float sz,
    float cx0, float cy0, float cz0,
    const float* __restrict__ vol,
    const float*& b, float& wx, float& wy, float& wz, bool& inside)
{
    const float fx = fmaf(fp, sx, cx0);
    const float fy = fmaf(fp, sy, cy0);
    const float fz = fmaf(fp, sz, cz0);
    const float mn = fminf(fminf(fx, fy), fz);
    const float mx = fmaxf(fmaxf(fx, fy), fz);
    inside = (mn >= 0.0f) & (mx <= 255.0f);
    const float fxc = fminf(fmaxf(fx, 0.0f), 254.0f);
    const float fyc = fminf(fmaxf(fy, 0.0f), 254.0f);
    const float fzc = fminf(fmaxf(fz, 0.0f), 254.0f);
    const int x0 = (int)fxc;
    const int y0 = (int)fyc;
    const int z0 = (int)fzc;
    wx = fx - (float)x0;
    wy = fy - (float)y0;
    wz = fz - (float)z0;
    b = vol + ((z0 << 16) + (y0 << 8) + x0);
}

// Interior-path sample: whole warp certainly inside (>= 1 integer step of
// margin past the slab crossing on every axis, which exceeds fp error), so
// fx,fy,fz in (0,255) strictly -> floor in [0,254]: NO clamps needed.
// Float-exact index math (idx < 2^24). A 2-op safety clamp on the linear
// index (never triggers) guards against any theoretical OOB fault.
__device__ __forceinline__ void interior_setup(
    float fp, float sx, float sy, float sz,
    float cx0, float cy0, float cz0,
    const float* __restrict__ vol,
    const float*& b, float& wx, float& wy, float& wz)
{
    const float fx = fmaf(fp, sx, cx0);
    const float fy = fmaf(fp, sy, cy0);
    const float fz = fmaf(fp, sz, cz0);
    const float x0f = floorf(fx);
    const float y0f = floorf(fy);
    const float z0f = floorf(fz);
    wx = fx - x0f;
    wy = fy - y0f;
    wz = fz - z0f;
    float idxf = fmaf(z0f, 65536.0f, fmaf(y0f, 256.0f, x0f));
    idxf = fminf(fmaxf(idxf, 0.0f), 16711934.0f);  // safety net only
    b = vol + (int)idxf;                           // exact: idx < 2^24
}

__device__ __forceinline__ float tri_tree(
    const float v[8], float wx, float wy, float wz)
{
    const float c00 = fmaf(wx, v[1] - v[0], v[0]);
    const float c01 = fmaf(wx, v[3] - v[2], v[2]);
    const float c10 = fmaf(wx, v[5] - v[4], v[4]);
    const float c11 = fmaf(wx, v[7] - v[6], v[6]);
    const float c0  = fmaf(wy, c01 - c00, c00);
    const float c1  = fmaf(wy, c11 - c10, c10);
    return fmaf(wz, c1 - c0, c0);
}

#define LOAD8(v, b)                 \
    v[0] = __ldg(b);                \
    v[1] = __ldg(b + 1);            \
    v[2] = __ldg(b + 256);          \
    v[3] = __ldg(b + 257);          \
    v[4] = __ldg(b + 65536);        \
    v[5] = __ldg(b + 65537);        \
    v[6] = __ldg(b + 65792);        \
    v[7] = __ldg(b + 65793);

// ===========================================================================
// Kernel 1: ray-march one depth chunk per block. block = half an image row
// (128 w), __launch_bounds__(128, 8) -> 32 warps/SM theoretical.
// grid = (512 half-rows, NC=8 chunks) -> 4096 small blocks for tail balance.
// Zones per chunk: masked edge | unmasked interior (PIPE=3) | masked edge.
// NOTE: the `if (ws <= we)` guard is LOAD-BEARING — when a whole warp has
// no samples, ws=INT_MAX and loop conditions would signed-overflow.
// ===========================================================================
__global__ __launch_bounds__(128, 8) void render_k(
    const float* __restrict__ vol,
    const float* __restrict__ camR,
    const float* __restrict__ camT)
{
    const int w = ((blockIdx.x & 1) << 7) + threadIdx.x;   // 0..255
    const int h = blockIdx.x >> 1;                          // 0..255
    const int c = blockIdx.y;

    const float gx = fmaf((float)w, 2.0f / 255.0f, -1.0f);
    const float gy = fmaf((float)h, 2.0f / 255.0f, -1.0f);
    const float dcx = gx * FOV_TAN;
    const float dcy = gy * FOV_TAN;

    const float R0 = camR[0], R1 = camR[1], R2 = camR[2];
    const float R3 = camR[3], R4 = camR[4], R5 = camR[5];
    const float R6 = camR[6], R7 = camR[7], R8 = camR[8];
    const float T0 = camT[0], T1 = camT[1], T2 = camT[2];

    const float ox = -(R0 * T0 + R3 * T1 + R6 * T2);
    const float oy = -(R1 * T0 + R4 * T1 + R7 * T2);
    const float oz = -(R2 * T0 + R5 * T1 + R8 * T2);
    const float dx = R0 * dcx + R3 * dcy + R6;
    const float dy = R1 * dcx + R4 * dcy + R7;
    const float dz = R2 * dcx + R5 * dcy + R8;

    // Voxel-space affine map:  f(p) = c0 + p*s   (depth = 2 + p*DSTEP)
    const float SC = 127.5f / HALF;
    const float cx0 = fmaf(fmaf(dx, 2.0f, ox), SC, 127.5f);
    const float cy0 = fmaf(fmaf(dy, 2.0f, oy), SC, 127.5f);
    const float cz0 = fmaf(fmaf(dz, 2.0f, oz), SC, 127.5f);
    const float sx = dx * (DSTEP * SC);
    const float sy = dy * (DSTEP * SC);
    const float sz = dz * (DSTEP * SC);

    // Per-ray slab bounds on p
    float tlo = -1e30f, thi = 1e30f;
    axis_bounds(cx0, sx, tlo, thi);
    axis_bounds(cy0, sy, tlo, thi);
    axis_bounds(cz0, sz, tlo, thi);

    int plo, phi;          // widened (masked) range
    int cin_lo, cin_hi;    // certainly-inside range (1-step margin)
    if (tlo > thi) {
        plo = 0x7fffffff; phi = -1;
        cin_lo = 1 << 29;  cin_hi = -(1 << 29);
    } else {
        plo = (int)floorf(fmaxf(tlo - 1.0f, 0.0f));
        phi = (int)ceilf (fminf(thi + 1.0f, 319.0f));
        const float tlo_c = fminf(fmaxf(tlo, -1.0f), 320.0f);
        const float thi_c = fminf(fmaxf(thi, -1.0f), 320.0f);
        cin_lo = (int)ceilf(tlo_c)  + 1;
        cin_hi = (int)floorf(thi_c) - 1;
    }

    const int p0 = c * CSTEP;
    int ps = max(p0, plo);
    int pe = min(p0 + CSTEP - 1, phi);
    const int ps_l = (ps <= pe) ? ps : 0x7fffffff;
    const int pe_l = (ps <= pe) ? pe : -1;
    const int ws = __reduce_min_sync(0xffffffffu, ps_l);
    const int we = __reduce_max_sync(0xffffffffu, pe_l);
    // warp intersection of certainly-inside ranges, clipped to chunk
    const int is = max(p0,             __reduce_max_sync(0xffffffffu, cin_lo));
    const int ie = min(p0 + CSTEP - 1, __reduce_min_sync(0xffffffffu, cin_hi));

    float Q   = 0.1f;    // 0.1 * transmittance
    float acc = 0.0f;

    if (ws <= we) {                       // guard (see kernel comment)
        const bool has_int = (is <= ie);
        const int  m1e = has_int ? min(is - 1, we) : we;
        int p = ws;

        // ---- masked leading edge ----
        for (; p <= m1e; p++) {
            const float* b0; float wx0, wy0, wz0; bool in0;
            sample_setup((float)p, sx, sy, sz, cx0, cy0, cz0, vol, b0, wx0, wy0, wz0, in0);
            float va[8];
            LOAD8(va, b0)
            const float s0 = tri_tree(va, wx0, wy0, wz0);
            acc = fmaf(in0 ? s0 : 0.0f, Q, acc);
            Q  *= in0 ? 0.9f : 1.0f;
        }

        // ---- unmasked interior (whole warp certainly inside) ----
        if (has_int) {
            for (; p + (PIPE - 1) <= ie; p += PIPE) {
                const float* b[PIPE];
                float wx[PIPE], wy[PIPE], wz[PIPE];
                #pragma unroll
                for (int k = 0; k < PIPE; k++)
                    interior_setup((float)(p + k), sx, sy, sz, cx0, cy0, cz0,
                                   vol, b[k], wx[k], wy[k], wz[k]);
                float v[PIPE][8];
                #pragma unroll
                for (int k = 0; k < PIPE; k++) {
                    LOAD8(v[k], b[k])
                }
                float s[PIPE];
                #pragma unroll
                for (int k = 0; k < PIPE; k++)
                    s[k] = tri_tree(v[k], wx[k], wy[k], wz[k]);
                #pragma unroll
                for (int k = 0; k < PIPE; k++) {
                    acc = fmaf(s[k], Q, acc);
                    Q  *= 0.9f;
                }
            }
            for (; p <= ie; p++) {
                const float* b0; float wx0, wy0, wz0;
                interior_setup((float)p, sx, sy, sz, cx0, cy0, cz0, vol, b0, wx0, wy0, wz0);
                float va[8];
                LOAD8(va, b0)
                acc = fmaf(tri_tree(va, wx0, wy0, wz0), Q, acc);
                Q  *= 0.9f;
            }
        }

        // ---- masked trailing edge ----
        for (; p <= we; p++) {
            const float* b0; float wx0, wy0, wz0; bool in0;
            sample_setup((float)p, sx, sy, sz, cx0, cy0, cz0, vol, b0, wx0, wy0, wz0, in0);
            float va[8];
            LOAD8(va, b0)
            const float s0 = tri_tree(va, wx0, wy0, wz0);
            acc = fmaf(in0 ? s0 : 0.0f, Q, acc);
            Q  *= in0 ? 0.9f : 1.0f;
        }
    }

    const int pix = (h << 8) + w;
    g_cRGB[c * NPIX + pix] = acc;
    g_cT[c * NPIX + pix]   = Q * 10.0f;   // reconstruct transmittance
}

// ===========================================================================
// Kernel 2: combine chunks front-to-back, store gray, per-block partials;
// LAST block (self-resetting counter) does the deterministic final reduction.
// ===========================================================================
__global__ __launch_bounds__(256) void combine_k()
{
    const int t   = threadIdx.x;
    const int pix = (blockIdx.x << 8) + t;

    float T = 1.0f, G = 0.0f;
    #pragma unroll
    for (int c = 0; c < NC; c++) {
        G = fmaf(T, g_cRGB[c * NPIX + pix], G);
        T *= g_cT[c * NPIX + pix];
    }
    g_gray[pix] = G;

    __shared__ float ssum[256], ssq[256], smin[256], smax[256];
    ssum[t] = G; ssq[t] = G * G; smin[t] = G; smax[t] = G;
    for (int o = 128; o > 0; o >>= 1) {
        __syncthreads();
        if (t < o) {
            ssum[t] += ssum[t + o];
            ssq[t]  += ssq[t + o];
            smin[t]  = fminf(smin[t], smin[t + o]);
            smax[t]  = fmaxf(smax[t], smax[t + o]);
        }
    }

    __shared__ bool last;
    if (t == 0) {
        g_psum[blockIdx.x] = ssum[0];
        g_psq[blockIdx.x]  = ssq[0];
        g_pmin[blockIdx.x] = smin[0];
        g_pmax[blockIdx.x] = smax[0];
        __threadfence();
        last = (atomicInc(&g_cnt, 255u) == 255u);   // wraps to 0: graph-replay safe
    }
    __syncthreads();
    if (!last) return;

    __shared__ double dsum[256], dsq[256];
    __shared__ float  fmn[256], fmx[256];
    dsum[t] = (double)g_psum[t];
    dsq[t]  = (double)g_psq[t];
    fmn[t]  = g_pmin[t];
    fmx[t]  = g_pmax[t];
    for (int o = 128; o > 0; o >>= 1) {
        __syncthreads();
        if (t < o) {
            dsum[t] += dsum[t + o];
            dsq[t]  += dsq[t + o];
            fmn[t]   = fminf(fmn[t], fmn[t + o]);
            fmx[t]   = fmaxf(fmx[t], fmx[t + o]);
        }
    }
    if (t == 0) {
        const double N = (double)NPIX;
        const double sum = dsum[0], sq = dsq[0];
        const double mean = sum / N;
        double var = (sq - sum * sum / N) / (N - 1.0);
        if (var < 0.0) var = 0.0;
        const float meanf = (float)mean;
        const float s     = (float)sqrt(var) + 1e-8f;     // sigma(ddof=1) + EPS
        const float stdmn = (fmn[0] - meanf) / s;
        const float stdmx = (fmx[0] - meanf) / s;
        g_scal[0] = meanf;
        g_scal[1] = s;
        g_scal[2] = stdmn;
        g_scal[3] = stdmx - stdmn + 1e-8f;                // denom
    }
}

// ===========================================================================
// Kernel 3: normalize + transpose, both sides coalesced via 32x32 smem tile.
// ===========================================================================
__global__ __launch_bounds__(256) void norm_k(float* __restrict__ out)
{
    __shared__ float tile[32][33];
    const int tx = threadIdx.x;          // 0..31
    const int ty = threadIdx.y;          // 0..7
    const int wbase = blockIdx.x << 5;
    const int hbase = blockIdx.y << 5;

    #pragma unroll
    for (int j = 0; j < 32; j += 8) {
        const int h = hbase + ty + j;
        tile[ty + j][tx] = g_gray[(h << 8) + wbase + tx];   // coalesced (w contiguous)
    }
    __syncthreads();

    const float mean  = g_scal[0];
    const float s     = g_scal[1];
    const float stdmn = g_scal[2];
    const float denom = g_scal[3];

    #pragma unroll
    for (int j = 0; j < 32; j += 8) {
        const int w = wbase + ty + j;
        const float g = tile[tx][ty + j];
        const float stdv = (g - mean) / s;
        out[(w << 8) + hbase + tx] = (stdv - stdmn + 1e-8f) / denom;  // coalesced (h contiguous)
    }
}

extern "C" void kernel_launch(void* const* d_in, const int* in_sizes, int n_in,
                              void* d_out, int out_size)
{
    const float* vol  = (const float*)d_in[0];   // image3d (1,1,256,256,256)
    const float* camR = (const float*)d_in[1];   // (1,3,3)
    const float* camT = (const float*)d_in[2];   // (1,3)
    float* out = (float*)d_out;                  // (1,1,256,256)

    render_k<<<dim3(512, NC), 128>>>(vol, camR, camT);
    combine_k<<<256, 256>>>();
    norm_k<<<dim3(8, 8), dim3(32, 8)>>>(out);
}

// round 14
// speedup vs baseline: 1.1139x; 1.1139x over previous
#include <cuda_runtime.h>

#define FOV_TAN 0.57735026918962576451f   // tan(30 deg)
#define HALF    1.494140625f              // 255 * (3/256) * 0.5
#define NC      5                         // depth chunks
#define CSTEP   64                        // 320 / NC
#define NPIX    65536
#define DSTEP   (4.0f / 319.0f)           // linspace(2,6,320) step
#define PIPE    3                         // interior pipeline width

// ---- scratch (static device arrays; no allocations allowed) ----
__device__ float g_cRGB[NC * NPIX];
__device__ float g_cT[NC * NPIX];
__device__ float g_gray[NPIX];
__device__ float g_psum[256], g_psq[256], g_pmin[256], g_pmax[256];
__device__ float g_scal[4];          // mean, sigma+eps, stdmin, denom
__device__ unsigned g_cnt = 0;       // self-resetting last-block counter

// longest-first chunk dispatch order (central depth chunks run longest)
__device__ __constant__ int c_chunk_perm[NC] = {2, 1, 3, 0, 4};

// Intersect f(p) = c0 + s*p with [0, 255]; accumulate into [tlo, thi].
__device__ __forceinline__ void axis_bounds(float c0, float s, float& tlo, float& thi)
{
    if (s > 0.0f) {
        tlo = fmaxf(tlo, (0.0f   - c0) / s);
        thi = fminf(thi, (255.0f - c0) / s);
    } else if (s < 0.0f) {
        tlo = fmaxf(tlo, (255.0f - c0) / s);
        thi = fminf(thi, (0.0f   - c0) / s);
    } else if (c0 < 0.0f || c0 > 255.0f) {
        tlo = 1e30f; thi = -1e30f;
    }
}

// Masked-path sample: coords -> clamped base + weights + inside mask.
__device__ __forceinline__ void sample_setup(
    float fp, float sx, float sy, float sz,
    float cx0, float cy0, float cz0,
    const float* __restrict__ vol,
    const float*& b, float& wx, float& wy, float& wz, bool& inside)
{
    const float fx = fmaf(fp, sx, cx0);
    const float fy = fmaf(fp, sy, cy0);
    const float fz = fmaf(fp, sz, cz0);
    const float mn = fminf(fminf(fx, fy), fz);
    const float mx = fmaxf(fmaxf(fx, fy), fz);
    inside = (mn >= 0.0f) & (mx <= 255.0f);
    const float fxc = fminf(fmaxf(fx, 0.0f), 254.0f);
    const float fyc = fminf(fmaxf(fy, 0.0f), 254.0f);
    const float fzc = fminf(fmaxf(fz, 0.0f), 254.0f);
    const int x0 = (int)fxc;
    const int y0 = (int)fyc;
    const int z0 = (int)fzc;
    wx = fx - (float)x0;
    wy = fy - (float)y0;
    wz = fz - (float)z0;
    b = vol + ((z0 << 16) + (y0 << 8) + x0);
}

// Interior-path sample: whole warp certainly inside (>= 1 integer step of
// margin past the slab crossing on every axis, exceeding fp error), so
// fx,fy,fz in (0,255) strictly -> floor in [0,254]: NO clamps needed.
// Float-exact index math (idx < 2^24). The 2-op safety clamp on the linear
// index never triggers; it only guards against a theoretical OOB fault.
__device__ __forceinline__ void interior_setup(
    float fp, float sx, float sy, float sz,
    float cx0, float cy0, float cz0,
    const float* __restrict__ vol,
    const float*& b, float& wx, float& wy, float& wz)
{
    const float fx = fmaf(fp, sx, cx0);
    const float fy = fmaf(fp, sy, cy0);
    const float fz = fmaf(fp, sz, cz0);
    const float x0f = floorf(fx);
    const float y0f = floorf(fy);
    const float z0f = floorf(fz);
    wx = fx - x0f;
    wy = fy - y0f;
    wz = fz - z0f;
    float idxf = fmaf(z0f, 65536.0f, fmaf(y0f, 256.0f, x0f));
    idxf = fminf(fmaxf(idxf, 0.0f), 16711934.0f);  // safety net only
    b = vol + (int)idxf;                           // exact: idx < 2^24
}

__device__ __forceinline__ float tri_tree(
    const float v[8], float wx, float wy, float wz)
{
    const float c00 = fmaf(wx, v[1] - v[0], v[0]);
    const float c01 = fmaf(wx, v[3] - v[2], v[2]);
    const float c10 = fmaf(wx, v[5] - v[4], v[4]);
    const float c11 = fmaf(wx, v[7] - v[6], v[6]);
    const float c0  = fmaf(wy, c01 - c00, c00);
    const float c1  = fmaf(wy, c11 - c10, c10);
    return fmaf(wz, c1 - c0, c0);
}

#define LOAD8(v, b)                 \
    v[0] = __ldg(b);                \
    v[1] = __ldg(b + 1);            \
    v[2] = __ldg(b + 256);          \
    v[3] = __ldg(b + 257);          \
    v[4] = __ldg(b + 65536);        \
    v[5] = __ldg(b + 65537);        \
    v[6] = __ldg(b + 65792);        \
    v[7] = __ldg(b + 65793);

// ===========================================================================
// Kernel 1: ray-march one depth chunk per block. block = one image row
// (256 w), grid = (256 rows, NC chunks), __launch_bounds__(256, 4).
// Longest-first dispatch: chunk perm {2,1,3,0,4}; rows center-out — the
// shortest (corner) blocks land in the drain tail.
// Zones per chunk: masked edge | unmasked interior (PIPE=3) | masked edge.
// NOTE: the `if (ws <= we)` guard is LOAD-BEARING — when a whole warp has
// no samples, ws=INT_MAX and loop conditions would signed-overflow.
// ===========================================================================
__global__ __launch_bounds__(256, 4) void render_k(
    const float* __restrict__ vol,
    const float* __restrict__ camR,
    const float* __restrict__ camT)
{
    const int w = threadIdx.x;
    // center-out row order: bid 0,1,2,3... -> h 127,128,126,129,...
    const int r = blockIdx.x >> 1;
    const int h = (blockIdx.x & 1) ? (128 + r) : (127 - r);
    const int c = c_chunk_perm[blockIdx.y];

    const float gx = fmaf((float)w, 2.0f / 255.0f, -1.0f);
    const float gy = fmaf((float)h, 2.0f / 255.0f, -1.0f);
    const float dcx = gx * FOV_TAN;
    const float dcy = gy * FOV_TAN;

    const float R0 = camR[0], R1 = camR[1], R2 = camR[2];
    const float R3 = camR[3], R4 = camR[4], R5 = camR[5];
    const float R6 = camR[6], R7 = camR[7], R8 = camR[8];
    const float T0 = camT[0], T1 = camT[1], T2 = camT[2];

    const float ox = -(R0 * T0 + R3 * T1 + R6 * T2);
    const float oy = -(R1 * T0 + R4 * T1 + R7 * T2);
    const float oz = -(R2 * T0 + R5 * T1 + R8 * T2);
    const float dx = R0 * dcx + R3 * dcy + R6;
    const float dy = R1 * dcx + R4 * dcy + R7;
    const float dz = R2 * dcx + R5 * dcy + R8;

    // Voxel-space affine map:  f(p) = c0 + p*s   (depth = 2 + p*DSTEP)
    const float SC = 127.5f / HALF;
    const float cx0 = fmaf(fmaf(dx, 2.0f, ox), SC, 127.5f);
    const float cy0 = fmaf(fmaf(dy, 2.0f, oy), SC, 127.5f);
    const float cz0 = fmaf(fmaf(dz, 2.0f, oz), SC, 127.5f);
    const float sx = dx * (DSTEP * SC);
    const float sy = dy * (DSTEP * SC);
    const float sz = dz * (DSTEP * SC);

    // Per-ray slab bounds on p
    float tlo = -1e30f, thi = 1e30f;
    axis_bounds(cx0, sx, tlo, thi);
    axis_bounds(cy0, sy, tlo, thi);
    axis_bounds(cz0, sz, tlo, thi);

    int plo, phi;          // widened (masked) range
    int cin_lo, cin_hi;    // certainly-inside range (1-step margin)
    if (tlo > thi) {
        plo = 0x7fffffff; phi = -1;
        cin_lo = 1 << 29;  cin_hi = -(1 << 29);
    } else {
        plo = (int)floorf(fmaxf(tlo - 1.0f, 0.0f));
        phi = (int)ceilf (fminf(thi + 1.0f, 319.0f));
        const float tlo_c = fminf(fmaxf(tlo, -1.0f), 320.0f);
        const float thi_c = fminf(fmaxf(thi, -1.0f), 320.0f);
        cin_lo = (int)ceilf(tlo_c)  + 1;
        cin_hi = (int)floorf(thi_c) - 1;
    }

    const int p0 = c * CSTEP;
    int ps = max(p0, plo);
    int pe = min(p0 + CSTEP - 1, phi);
    const int ps_l = (ps <= pe) ? ps : 0x7fffffff;
    const int pe_l = (ps <= pe) ? pe : -1;
    const int ws = __reduce_min_sync(0xffffffffu, ps_l);
    const int we = __reduce_max_sync(0xffffffffu, pe_l);
    // warp intersection of certainly-inside ranges, clipped to chunk
    const int is = max(p0,             __reduce_max_sync(0xffffffffu, cin_lo));
    const int ie = min(p0 + CSTEP - 1, __reduce_min_sync(0xffffffffu, cin_hi));

    float Q   = 0.1f;    // 0.1 * transmittance
    float acc = 0.0f;

    if (ws <= we) {                       // guard (see kernel comment)
        const bool has_int = (is <= ie);
        const int  m1e = has_int ? min(is - 1, we) : we;
        int p = ws;

        // ---- masked leading edge ----
        for (; p <= m1e; p++) {
            const float* b0; float wx0, wy0, wz0; bool in0;
            sample_setup((float)p, sx, sy, sz, cx0, cy0, cz0, vol, b0, wx0, wy0, wz0, in0);
            float va[8];
            LOAD8(va, b0)
            const float s0 = tri_tree(va, wx0, wy0, wz0);
            acc = fmaf(in0 ? s0 : 0.0f, Q, acc);
            Q  *= in0 ? 0.9f : 1.0f;
        }

        // ---- unmasked interior (whole warp certainly inside) ----
        if (has_int) {
            for (; p + (PIPE - 1) <= ie; p += PIPE) {
                const float* b[PIPE];
                float wx[PIPE], wy[PIPE], wz[PIPE];
                #pragma unroll
                for (int k = 0; k < PIPE; k++)
                    interior_setup((float)(p + k), sx, sy, sz, cx0, cy0, cz0,
                                   vol, b[k], wx[k], wy[k], wz[k]);
                float v[PIPE][8];
                #pragma unroll
                for (int k = 0; k < PIPE; k++) {
                    LOAD8(v[k], b[k])
                }
                float s[PIPE];
                #pragma unroll
                for (int k = 0; k < PIPE; k++)
                    s[k] = tri_tree(v[k], wx[k], wy[k], wz[k]);
                #pragma unroll
                for (int k = 0; k < PIPE; k++) {
                    acc = fmaf(s[k], Q, acc);
                    Q  *= 0.9f;
                }
            }
            for (; p <= ie; p++) {
                const float* b0; float wx0, wy0, wz0;
                interior_setup((float)p, sx, sy, sz, cx0, cy0, cz0, vol, b0, wx0, wy0, wz0);
                float va[8];
                LOAD8(va, b0)
                acc = fmaf(tri_tree(va, wx0, wy0, wz0), Q, acc);
                Q  *= 0.9f;
            }
        }

        // ---- masked trailing edge ----
        for (; p <= we; p++) {
            const float* b0; float wx0, wy0, wz0; bool in0;
            sample_setup((float)p, sx, sy, sz, cx0, cy0, cz0, vol, b0, wx0, wy0, wz0, in0);
            float va[8];
            LOAD8(va, b0)
            const float s0 = tri_tree(va, wx0, wy0, wz0);
            acc = fmaf(in0 ? s0 : 0.0f, Q, acc);
            Q  *= in0 ? 0.9f : 1.0f;
        }
    }

    const int pix = (h << 8) + w;
    g_cRGB[c * NPIX + pix] = acc;
    g_cT[c * NPIX + pix]   = Q * 10.0f;   // reconstruct transmittance
}

// ===========================================================================
// Kernel 2: combine chunks front-to-back, store gray, per-block partials;
// LAST block (self-resetting counter) does the deterministic final reduction.
// ===========================================================================
__global__ __launch_bounds__(256) void combine_k()
{
    const int t   = threadIdx.x;
    const int pix = (blockIdx.x << 8) + t;

    float T = 1.0f, G = 0.0f;
    #pragma unroll
    for (int c = 0; c < NC; c++) {
        G = fmaf(T, g_cRGB[c * NPIX + pix], G);
        T *= g_cT[c * NPIX + pix];
    }
    g_gray[pix] = G;

    __shared__ float ssum[256], ssq[256], smin[256], smax[256];
    ssum[t] = G; ssq[t] = G * G; smin[t] = G; smax[t] = G;
    for (int o = 128; o > 0; o >>= 1) {
        __syncthreads();
        if (t < o) {
            ssum[t] += ssum[t + o];
            ssq[t]  += ssq[t + o];
            smin[t]  = fminf(smin[t], smin[t + o]);
            smax[t]  = fmaxf(smax[t], smax[t + o]);
        }
    }

    __shared__ bool last;
    if (t == 0) {
        g_psum[blockIdx.x] = ssum[0];
        g_psq[blockIdx.x]  = ssq[0];
        g_pmin[blockIdx.x] = smin[0];
        g_pmax[blockIdx.x] = smax[0];
        __threadfence();
        last = (atomicInc(&g_cnt, 255u) == 255u);   // wraps to 0: graph-replay safe
    }
    __syncthreads();
    if (!last) return;

    __shared__ double dsum[256], dsq[256];
    __shared__ float  fmn[256], fmx[256];
    dsum[t] = (double)g_psum[t];
    dsq[t]  = (double)g_psq[t];
    fmn[t]  = g_pmin[t];
    fmx[t]  = g_pmax[t];
    for (int o = 128; o > 0; o >>= 1) {
        __syncthreads();
        if (t < o) {
            dsum[t] += dsum[t + o];
            dsq[t]  += dsq[t + o];
            fmn[t]   = fminf(fmn[t], fmn[t + o]);
            fmx[t]   = fmaxf(fmx[t], fmx[t + o]);
        }
    }
    if (t == 0) {
        const double N = (double)NPIX;
        const double sum = dsum[0], sq = dsq[0];
        const double mean = sum / N;
        double var = (sq - sum * sum / N) / (N - 1.0);
        if (var < 0.0) var = 0.0;
        const float meanf = (float)mean;
        const float s     = (float)sqrt(var) + 1e-8f;     // sigma(ddof=1) + EPS
        const float stdmn = (fmn[0] - meanf) / s;
        const float stdmx = (fmx[0] - meanf) / s;
        g_scal[0] = meanf;
        g_scal[1] = s;
        g_scal[2] = stdmn;
        g_scal[3] = stdmx - stdmn + 1e-8f;                // denom
    }
}

// ===========================================================================
// Kernel 3: normalize + transpose, both sides coalesced via 32x32 smem tile.
// ===========================================================================
__global__ __launch_bounds__(256) void norm_k(float* __restrict__ out)
{
    __shared__ float tile[32][33];
    const int tx = threadIdx.x;          // 0..31
    const int ty = threadIdx.y;          // 0..7
    const int wbase = blockIdx.x << 5;
    const int hbase = blockIdx.y << 5;

    #pragma unroll
    for (int j = 0; j < 32; j += 8) {
        const int h = hbase + ty + j;
        tile[ty + j][tx] = g_gray[(h << 8) + wbase + tx];   // coalesced (w contiguous)
    }
    __syncthreads();

    const float mean  = g_scal[0];
    const float s     = g_scal[1];
    const float stdmn = g_scal[2];
    const float denom = g_scal[3];

    #pragma unroll
    for (int j = 0; j < 32; j += 8) {
        const int w = wbase + ty + j;
        const float g = tile[tx][ty + j];
        const float stdv = (g - mean) / s;
        out[(w << 8) + hbase + tx] = (stdv - stdmn + 1e-8f) / denom;  // coalesced (h contiguous)
    }
}

extern "C" void kernel_launch(void* const* d_in, const int* in_sizes, int n_in,
                              void* d_out, int out_size)
{
    const float* vol  = (const float*)d_in[0];   // image3d (1,1,256,256,256)
    const float* camR = (const float*)d_in[1];   // (1,3,3)
    const float* camT = (const float*)d_in[2];   // (1,3)
    float* out = (float*)d_out;                  // (1,1,256,256)

    render_k<<<dim3(256, NC), 256>>>(vol, camR, camT);
    combine_k<<<256, 256>>>();
    norm_k<<<dim3(8, 8), dim3(32, 8)>>>(out);
}